// round 6
// baseline (speedup 1.0000x reference)
#include <cuda_runtime.h>

// ---------------- NAVAR dims ----------------
#define ND      2
#define NS      4
#define NV      12
#define HID     16
#define GROUPS  96
#define KS      4
#define T       2048
#define BATCH   8

// ---------------- tiling ----------------
#define TT      228              // output timesteps per tile
#define HALO    28               // 3 + 3*(1+2+4)
#define LL      (TT + HALO)      // 256 local positions
#define PITCH   260              // row pitch (floats)
#define NTHREADS 256
#define NTILES  9
#define PRED_ELEMS (BATCH*ND*NS*NV*T)        // 1,572,864
#define GUARD   16               // floats of scratch before bufA (negative-j reads)

typedef unsigned long long u64;

// ---- packed f32x2 helpers (Blackwell) ----
__device__ __forceinline__ u64 pk2(float a, float b) {
    u64 r; asm("mov.b64 %0, {%1, %2};" : "=l"(r) : "f"(a), "f"(b)); return r;
}
__device__ __forceinline__ u64 dup2f(float a) {
    u64 r; asm("mov.b64 %0, {%1, %1};" : "=l"(r) : "f"(a)); return r;
}
__device__ __forceinline__ void fma2(u64 &d, u64 a, u64 b) {
    asm("fma.rn.f32x2 %0, %1, %2, %0;" : "+l"(d) : "l"(a), "l"(b));
}
__device__ __forceinline__ void unpk(u64 v, float &lo, float &hi) {
    asm("mov.b64 {%0, %1}, %2;" : "=f"(lo), "=f"(hi) : "l"(v));
}

struct __align__(16) Smem {
    float bufs[GUARD + 2 * HID * PITCH]; // bufA, bufB back-to-back   33,344 B
    float xsb[4 + PITCH];                //                             1,056 B
    u64   whp[3][HID * 8 * KS];          // all 3 layers co-paired     12,288 B
    u64   woutp[HID * 6];                //                               768 B
    u64   boutp[6];                      //                                48 B
    float w_in[HID * KS];                //                               256 B
    float b_in[HID];                     //                                64 B
    float b_h[3 * HID];                  //                               192 B
};  // 48,016 B < 48 KB static limit; x3 CTAs = 144 KB/SM

// ---- hidden conv HID->HID dilation D, co-paired (proven R3 scheme) ----
// warp: cg=wid>>2 -> co 8*cg..8*cg+7 (4 packed pairs); tq=wid&3 -> j1=tq*64+lane,
// j2=j1+32.  Lane->j contiguous: all data LDS conflict-free, weights broadcast.
template<int D, int S>
__device__ __forceinline__ void hidden_cp(
    const float* __restrict__ in, float* __restrict__ out,
    const u64* __restrict__ wp, const float* __restrict__ bl,
    int gt0, int lane, int wid)
{
    const int cg = wid >> 2;
    const int tq = wid & 3;
    const int j1 = tq * 64 + lane;
    const int j2 = j1 + 32;

    u64 acc[4][2];
    #pragma unroll
    for (int p = 0; p < 4; p++) {
        u64 bp = pk2(bl[cg * 8 + 2 * p], bl[cg * 8 + 2 * p + 1]);
        acc[p][0] = bp; acc[p][1] = bp;
    }

    #pragma unroll 2
    for (int ci = 0; ci < HID; ci++) {
        const float* row = in + ci * PITCH;
        u64 vda[4], vdb[4];
        #pragma unroll
        for (int k = 0; k < 4; k++) {
            vda[k] = dup2f(row[j1 + (k - 3) * D]);
            vdb[k] = dup2f(row[j2 + (k - 3) * D]);
        }
        const ulonglong2* w2 = (const ulonglong2*)(wp + ci * 32 + cg * 16);
        #pragma unroll
        for (int p = 0; p < 4; p++) {
            ulonglong2 wa = w2[2 * p], wb = w2[2 * p + 1];
            fma2(acc[p][0], wa.x, vda[0]); fma2(acc[p][1], wa.x, vdb[0]);
            fma2(acc[p][0], wa.y, vda[1]); fma2(acc[p][1], wa.y, vdb[1]);
            fma2(acc[p][0], wb.x, vda[2]); fma2(acc[p][1], wb.x, vdb[2]);
            fma2(acc[p][0], wb.y, vda[3]); fma2(acc[p][1], wb.y, vdb[3]);
        }
    }

    #pragma unroll
    for (int p = 0; p < 4; p++) {
        const int co0 = cg * 8 + 2 * p;
        float a0, a1, c0, c1;
        unpk(acc[p][0], a0, a1);
        unpk(acc[p][1], c0, c1);
        if (j1 >= S) {
            bool z = (gt0 + j1) < 0;
            out[co0 * PITCH + j1]       = z ? 0.f : fmaxf(a0, 0.f);
            out[(co0 + 1) * PITCH + j1] = z ? 0.f : fmaxf(a1, 0.f);
        }
        {
            bool z = (gt0 + j2) < 0;
            out[co0 * PITCH + j2]       = z ? 0.f : fmaxf(c0, 0.f);
            out[(co0 + 1) * PITCH + j2] = z ? 0.f : fmaxf(c1, 0.f);
        }
    }
}

__global__ void __launch_bounds__(NTHREADS, 3)
navar_main_kernel(const float* __restrict__ x,
                  const float* __restrict__ w_in, const float* __restrict__ b_in,
                  const float* __restrict__ w_h,  const float* __restrict__ b_h,
                  const float* __restrict__ w_out,const float* __restrict__ b_out,
                  float* __restrict__ out_contrib)
{
    __shared__ Smem s;
    float* bufA = s.bufs + GUARD;
    float* bufB = bufA + HID * PITCH;
    float* xs   = s.xsb + 4;

    const int tile = blockIdx.x;
    const int g    = blockIdx.y;
    const int b    = blockIdx.z;
    const int t0   = tile * TT;
    const int gt0  = t0 - HALO;
    const int tid  = threadIdx.x;
    const int lane = tid & 31;
    const int wid  = tid >> 5;

    // ---- stage x tile + all params (all 3 hidden layers prestaged) ----
    const float* xg = x + ((size_t)b * GROUPS + g) * T;
    for (int j = tid; j < PITCH; j += NTHREADS) {
        int gt = gt0 + j;
        xs[j] = (gt >= 0 && gt < T) ? xg[gt] : 0.f;
    }
    if (tid < HID * KS) s.w_in[tid] = w_in[g * HID * KS + tid];
    if (tid < HID)      s.b_in[tid] = b_in[g * HID + tid];
    for (int i = tid; i < 3 * HID; i += NTHREADS) {
        int L = i >> 4, co = i & 15;
        s.b_h[i] = b_h[L * GROUPS * HID + g * HID + co];
    }
    for (int i = tid; i < HID * 6 * 2; i += NTHREADS) {
        int half = i & 1, dp = (i >> 1) % 6, ci = (i >> 1) / 6;
        ((float*)s.woutp)[i] = w_out[((size_t)g * NV + 2 * dp + half) * HID + ci];
    }
    if (tid < 12) {
        int half = tid & 1, dp = tid >> 1;
        ((float*)s.boutp)[tid] = b_out[g * NV + 2 * dp + half];
    }
    // hidden weights, co-paired: whp[L][(ci*8+pg)*4+k] = (w[2pg][ci][k], w[2pg+1][ci][k])
    #pragma unroll 1
    for (int L = 0; L < 3; L++) {
        const float* wsrc = w_h + ((size_t)L * GROUPS * HID + (size_t)g * HID) * (HID * KS);
        float* wdst = (float*)s.whp[L];
        #pragma unroll
        for (int r = 0; r < 4; r++) {
            int i = tid + r * NTHREADS;       // 0..1023
            int half = i & 1, k = (i >> 1) & 3, pg = (i >> 3) & 7, ci = i >> 6;
            wdst[i] = wsrc[((2 * pg + half) * HID + ci) * KS + k];
        }
    }
    __syncthreads();

    // ---- input conv 1 -> HID (thread = timestep j) -> bufA ----
    {
        const int j = tid;
        float xv0 = xs[j - 3], xv1 = xs[j - 2], xv2 = xs[j - 1], xv3 = xs[j];
        const bool neg = (gt0 + j) < 0;
        #pragma unroll
        for (int co = 0; co < HID; co++) {
            float4 w = *(const float4*)(s.w_in + co * 4);
            float a = s.b_in[co];
            a = fmaf(w.x, xv0, a); a = fmaf(w.y, xv1, a);
            a = fmaf(w.z, xv2, a); a = fmaf(w.w, xv3, a);
            bufA[co * PITCH + j] = neg ? 0.f : fmaxf(a, 0.f);
        }
    }
    __syncthreads();

    hidden_cp<1,  8>(bufA, bufB, s.whp[0], s.b_h,           gt0, lane, wid);
    __syncthreads();
    hidden_cp<2, 16>(bufB, bufA, s.whp[1], s.b_h + HID,     gt0, lane, wid);
    __syncthreads();
    hidden_cp<4, 28>(bufA, bufB, s.whp[2], s.b_h + 2 * HID, gt0, lane, wid);
    __syncthreads();

    // ---- 1x1 output conv: thread = timestep, 12 dst as 6 packed pairs ----
    {
        const int dd  = g / (NS * NV);
        const int rem = g % (NS * NV);
        const int ss  = rem / NV;
        const int src = rem % NV;
        const size_t cbase = ((size_t)((b * ND + dd) * NS + ss) * NV * NV + src) * T;

        const int trel = tid;
        const int gt   = t0 + trel;
        const bool act = (trel < TT) && (gt < T);
        const int jc   = act ? (HALO + trel) : HALO;

        u64 a6[6];
        #pragma unroll
        for (int dp = 0; dp < 6; dp++) a6[dp] = s.boutp[dp];

        #pragma unroll
        for (int ci = 0; ci < HID; ci++) {
            u64 hd = dup2f(bufB[ci * PITCH + jc]);
            const ulonglong2* w2 = (const ulonglong2*)(s.woutp + ci * 6);
            ulonglong2 wA = w2[0], wB = w2[1], wC = w2[2];
            fma2(a6[0], wA.x, hd); fma2(a6[1], wA.y, hd);
            fma2(a6[2], wB.x, hd); fma2(a6[3], wB.y, hd);
            fma2(a6[4], wC.x, hd); fma2(a6[5], wC.y, hd);
        }
        if (act) {
            #pragma unroll
            for (int dp = 0; dp < 6; dp++) {
                float lo, hi; unpk(a6[dp], lo, hi);
                out_contrib[cbase + (size_t)(2 * dp)     * NV * T + gt] = lo;
                out_contrib[cbase + (size_t)(2 * dp + 1) * NV * T + gt] = hi;
            }
        }
    }
}

// prediction[b,dd,ss,v,t] = sum_src contrib[b,dd,ss,v,src,t] + biases[dd,ss,v]
__global__ void __launch_bounds__(256)
navar_pred_kernel(const float4* __restrict__ contrib4,
                  const float* __restrict__ biases,
                  float4* __restrict__ pred4)
{
    int idx = blockIdx.x * blockDim.x + threadIdx.x;
    if (idx >= PRED_ELEMS / 4) return;
    int t4 = idx & (T / 4 - 1);
    int r  = idx >> 9;                 // T/4 = 512
    float bsc = biases[r % (ND * NS * NV)];
    const float4* cp = contrib4 + (size_t)r * NV * (T / 4) + t4;
    float4 acc = make_float4(bsc, bsc, bsc, bsc);
    #pragma unroll
    for (int sI = 0; sI < NV; sI++) {
        float4 v = cp[(size_t)sI * (T / 4)];
        acc.x += v.x; acc.y += v.y; acc.z += v.z; acc.w += v.w;
    }
    pred4[idx] = acc;
}

extern "C" void kernel_launch(void* const* d_in, const int* in_sizes, int n_in,
                              void* d_out, int out_size)
{
    const float* x      = (const float*)d_in[0];
    const float* w_in   = (const float*)d_in[1];
    const float* b_in   = (const float*)d_in[2];
    const float* w_h    = (const float*)d_in[3];
    const float* b_h    = (const float*)d_in[4];
    const float* w_out  = (const float*)d_in[5];
    const float* b_out  = (const float*)d_in[6];
    const float* biases = (const float*)d_in[7];

    float* out     = (float*)d_out;
    float* pred    = out;                     // (B,ND,NS,NV,T)
    float* contrib = out + PRED_ELEMS;        // (B,ND,NS,NV,NV,T)

    dim3 grid(NTILES, GROUPS, BATCH);
    navar_main_kernel<<<grid, NTHREADS>>>(x, w_in, b_in, w_h, b_h, w_out, b_out, contrib);
    navar_pred_kernel<<<(PRED_ELEMS / 4 + 255) / 256, 256>>>(
        (const float4*)contrib, biases, (float4*)pred);
}

// round 7
// speedup vs baseline: 1.0356x; 1.0356x over previous
#include <cuda_runtime.h>

// ---------------- NAVAR dims ----------------
#define ND      2
#define NS      4
#define NV      12
#define HID     16
#define GROUPS  96
#define KS      4
#define T       2048
#define BATCH   8

// ---------------- tiling ----------------
#define TT      228              // output timesteps per tile
#define HALO    28               // 3 + 3*(1+2+4)
#define LL      (TT + HALO)      // 256 local positions
#define PITCH   260              // row pitch (floats)
#define NTHREADS 256
#define NTILES  9
#define PRED_ELEMS (BATCH*ND*NS*NV*T)        // 1,572,864
#define GUARD   16               // floats of scratch before bufA (negative-j reads)

typedef unsigned long long u64;

// ---- packed f32x2 helpers (Blackwell) ----
__device__ __forceinline__ u64 pk2(float a, float b) {
    u64 r; asm("mov.b64 %0, {%1, %2};" : "=l"(r) : "f"(a), "f"(b)); return r;
}
__device__ __forceinline__ u64 dup2f(float a) {
    u64 r; asm("mov.b64 %0, {%1, %1};" : "=l"(r) : "f"(a)); return r;
}
__device__ __forceinline__ void fma2(u64 &d, u64 a, u64 b) {
    asm("fma.rn.f32x2 %0, %1, %2, %0;" : "+l"(d) : "l"(a), "l"(b));
}
__device__ __forceinline__ void unpk(u64 v, float &lo, float &hi) {
    asm("mov.b64 {%0, %1}, %2;" : "=f"(lo), "=f"(hi) : "l"(v));
}

struct __align__(16) Smem {
    float bufs[GUARD + 2 * HID * PITCH]; // bufA, bufB back-to-back   33,344 B
    float xsb[4 + PITCH];                //                             1,056 B
    u64   whp[3][HID * 8 * KS];          // all 3 layers co-paired     12,288 B
    u64   woutp[HID * 6];                //                               768 B
    u64   boutp[6];                      //                                48 B
    float w_in[HID * KS];                //                               256 B
    float b_in[HID];                     //                                64 B
    float b_h[3 * HID];                  //                               192 B
};  // 48,016 B; x4 CTAs = 187.6 KB/SM

// ---- hidden conv HID->HID dilation D, co-paired (proven scheme) ----
// warp: cg=wid>>2 -> co 8*cg..8*cg+7 (4 packed pairs); tq=wid&3 -> j1=tq*64+lane,
// j2=j1+32.  Lane->j contiguous: all data LDS conflict-free, weights broadcast.
template<int D, int S>
__device__ __forceinline__ void hidden_cp(
    const float* __restrict__ in, float* __restrict__ out,
    const u64* __restrict__ wp, const float* __restrict__ bl,
    int gt0, int lane, int wid)
{
    const int cg = wid >> 2;
    const int tq = wid & 3;
    const int j1 = tq * 64 + lane;
    const int j2 = j1 + 32;

    u64 acc[4][2];
    #pragma unroll
    for (int p = 0; p < 4; p++) {
        u64 bp = pk2(bl[cg * 8 + 2 * p], bl[cg * 8 + 2 * p + 1]);
        acc[p][0] = bp; acc[p][1] = bp;
    }

    #pragma unroll 2
    for (int ci = 0; ci < HID; ci++) {
        const float* row = in + ci * PITCH;
        u64 vda[4], vdb[4];
        #pragma unroll
        for (int k = 0; k < 4; k++) {
            vda[k] = dup2f(row[j1 + (k - 3) * D]);
            vdb[k] = dup2f(row[j2 + (k - 3) * D]);
        }
        const ulonglong2* w2 = (const ulonglong2*)(wp + ci * 32 + cg * 16);
        #pragma unroll
        for (int p = 0; p < 4; p++) {
            ulonglong2 wa = w2[2 * p], wb = w2[2 * p + 1];
            fma2(acc[p][0], wa.x, vda[0]); fma2(acc[p][1], wa.x, vdb[0]);
            fma2(acc[p][0], wa.y, vda[1]); fma2(acc[p][1], wa.y, vdb[1]);
            fma2(acc[p][0], wb.x, vda[2]); fma2(acc[p][1], wb.x, vdb[2]);
            fma2(acc[p][0], wb.y, vda[3]); fma2(acc[p][1], wb.y, vdb[3]);
        }
    }

    #pragma unroll
    for (int p = 0; p < 4; p++) {
        const int co0 = cg * 8 + 2 * p;
        float a0, a1, c0, c1;
        unpk(acc[p][0], a0, a1);
        unpk(acc[p][1], c0, c1);
        if (j1 >= S) {
            bool z = (gt0 + j1) < 0;
            out[co0 * PITCH + j1]       = z ? 0.f : fmaxf(a0, 0.f);
            out[(co0 + 1) * PITCH + j1] = z ? 0.f : fmaxf(a1, 0.f);
        }
        {
            bool z = (gt0 + j2) < 0;
            out[co0 * PITCH + j2]       = z ? 0.f : fmaxf(c0, 0.f);
            out[(co0 + 1) * PITCH + j2] = z ? 0.f : fmaxf(c1, 0.f);
        }
    }
}

__global__ void __launch_bounds__(NTHREADS, 4)
navar_main_kernel(const float* __restrict__ x,
                  const float* __restrict__ w_in, const float* __restrict__ b_in,
                  const float* __restrict__ w_h,  const float* __restrict__ b_h,
                  const float* __restrict__ w_out,const float* __restrict__ b_out,
                  float* __restrict__ out_contrib)
{
    __shared__ Smem s;
    float* bufA = s.bufs + GUARD;
    float* bufB = bufA + HID * PITCH;
    float* xs   = s.xsb + 4;

    const int tile = blockIdx.x;
    const int g    = blockIdx.y;
    const int b    = blockIdx.z;
    const int t0   = tile * TT;
    const int gt0  = t0 - HALO;
    const int tid  = threadIdx.x;
    const int lane = tid & 31;
    const int wid  = tid >> 5;

    // ---- stage x tile + all params (all 3 hidden layers prestaged) ----
    const float* xg = x + ((size_t)b * GROUPS + g) * T;
    for (int j = tid; j < PITCH; j += NTHREADS) {
        int gt = gt0 + j;
        xs[j] = (gt >= 0 && gt < T) ? xg[gt] : 0.f;
    }
    if (tid < HID * KS) s.w_in[tid] = w_in[g * HID * KS + tid];
    if (tid < HID)      s.b_in[tid] = b_in[g * HID + tid];
    for (int i = tid; i < 3 * HID; i += NTHREADS) {
        int L = i >> 4, co = i & 15;
        s.b_h[i] = b_h[L * GROUPS * HID + g * HID + co];
    }
    for (int i = tid; i < HID * 6 * 2; i += NTHREADS) {
        int half = i & 1, dp = (i >> 1) % 6, ci = (i >> 1) / 6;
        ((float*)s.woutp)[i] = w_out[((size_t)g * NV + 2 * dp + half) * HID + ci];
    }
    if (tid < 12) {
        int half = tid & 1, dp = tid >> 1;
        ((float*)s.boutp)[tid] = b_out[g * NV + 2 * dp + half];
    }
    // hidden weights, co-paired: whp[L][(ci*8+pg)*4+k] = (w[2pg][ci][k], w[2pg+1][ci][k])
    #pragma unroll 1
    for (int L = 0; L < 3; L++) {
        const float* wsrc = w_h + ((size_t)L * GROUPS * HID + (size_t)g * HID) * (HID * KS);
        float* wdst = (float*)s.whp[L];
        #pragma unroll
        for (int r = 0; r < 4; r++) {
            int i = tid + r * NTHREADS;       // 0..1023
            int half = i & 1, k = (i >> 1) & 3, pg = (i >> 3) & 7, ci = i >> 6;
            wdst[i] = wsrc[((2 * pg + half) * HID + ci) * KS + k];
        }
    }
    __syncthreads();

    // ---- input conv 1 -> HID (thread = timestep j) -> bufA ----
    {
        const int j = tid;
        float xv0 = xs[j - 3], xv1 = xs[j - 2], xv2 = xs[j - 1], xv3 = xs[j];
        const bool neg = (gt0 + j) < 0;
        #pragma unroll
        for (int co = 0; co < HID; co++) {
            float4 w = *(const float4*)(s.w_in + co * 4);
            float a = s.b_in[co];
            a = fmaf(w.x, xv0, a); a = fmaf(w.y, xv1, a);
            a = fmaf(w.z, xv2, a); a = fmaf(w.w, xv3, a);
            bufA[co * PITCH + j] = neg ? 0.f : fmaxf(a, 0.f);
        }
    }
    __syncthreads();

    hidden_cp<1,  8>(bufA, bufB, s.whp[0], s.b_h,           gt0, lane, wid);
    __syncthreads();
    hidden_cp<2, 16>(bufB, bufA, s.whp[1], s.b_h + HID,     gt0, lane, wid);
    __syncthreads();
    hidden_cp<4, 28>(bufA, bufB, s.whp[2], s.b_h + 2 * HID, gt0, lane, wid);
    __syncthreads();

    // ---- 1x1 output conv: thread = timestep, 12 dst as 6 packed pairs ----
    {
        const int dd  = g / (NS * NV);
        const int rem = g % (NS * NV);
        const int ss  = rem / NV;
        const int src = rem % NV;
        const size_t cbase = ((size_t)((b * ND + dd) * NS + ss) * NV * NV + src) * T;

        const int trel = tid;
        const int gt   = t0 + trel;
        const bool act = (trel < TT) && (gt < T);
        const int jc   = act ? (HALO + trel) : HALO;

        u64 a6[6];
        #pragma unroll
        for (int dp = 0; dp < 6; dp++) a6[dp] = s.boutp[dp];

        #pragma unroll
        for (int ci = 0; ci < HID; ci++) {
            u64 hd = dup2f(bufB[ci * PITCH + jc]);
            const ulonglong2* w2 = (const ulonglong2*)(s.woutp + ci * 6);
            ulonglong2 wA = w2[0], wB = w2[1], wC = w2[2];
            fma2(a6[0], wA.x, hd); fma2(a6[1], wA.y, hd);
            fma2(a6[2], wB.x, hd); fma2(a6[3], wB.y, hd);
            fma2(a6[4], wC.x, hd); fma2(a6[5], wC.y, hd);
        }
        if (act) {
            #pragma unroll
            for (int dp = 0; dp < 6; dp++) {
                float lo, hi; unpk(a6[dp], lo, hi);
                out_contrib[cbase + (size_t)(2 * dp)     * NV * T + gt] = lo;
                out_contrib[cbase + (size_t)(2 * dp + 1) * NV * T + gt] = hi;
            }
        }
    }
}

// prediction[b,dd,ss,v,t] = sum_src contrib[b,dd,ss,v,src,t] + biases[dd,ss,v]
__global__ void __launch_bounds__(256)
navar_pred_kernel(const float4* __restrict__ contrib4,
                  const float* __restrict__ biases,
                  float4* __restrict__ pred4)
{
    int idx = blockIdx.x * blockDim.x + threadIdx.x;
    if (idx >= PRED_ELEMS / 4) return;
    int t4 = idx & (T / 4 - 1);
    int r  = idx >> 9;                 // T/4 = 512
    float bsc = biases[r % (ND * NS * NV)];
    const float4* cp = contrib4 + (size_t)r * NV * (T / 4) + t4;
    float4 acc = make_float4(bsc, bsc, bsc, bsc);
    #pragma unroll
    for (int sI = 0; sI < NV; sI++) {
        float4 v = cp[(size_t)sI * (T / 4)];
        acc.x += v.x; acc.y += v.y; acc.z += v.z; acc.w += v.w;
    }
    pred4[idx] = acc;
}

extern "C" void kernel_launch(void* const* d_in, const int* in_sizes, int n_in,
                              void* d_out, int out_size)
{
    const float* x      = (const float*)d_in[0];
    const float* w_in   = (const float*)d_in[1];
    const float* b_in   = (const float*)d_in[2];
    const float* w_h    = (const float*)d_in[3];
    const float* b_h    = (const float*)d_in[4];
    const float* w_out  = (const float*)d_in[5];
    const float* b_out  = (const float*)d_in[6];
    const float* biases = (const float*)d_in[7];

    float* out     = (float*)d_out;
    float* pred    = out;                     // (B,ND,NS,NV,T)
    float* contrib = out + PRED_ELEMS;        // (B,ND,NS,NV,NV,T)

    dim3 grid(NTILES, GROUPS, BATCH);
    navar_main_kernel<<<grid, NTHREADS>>>(x, w_in, b_in, w_h, b_h, w_out, b_out, contrib);
    navar_pred_kernel<<<(PRED_ELEMS / 4 + 255) / 256, 256>>>(
        (const float4*)contrib, biases, (float4*)pred);
}

// round 8
// speedup vs baseline: 1.1372x; 1.0981x over previous
#include <cuda_runtime.h>

// ---------------- NAVAR dims ----------------
#define ND      2
#define NS      4
#define NV      12
#define HID     16
#define GROUPS  96
#define KS      4
#define T       2048
#define BATCH   8

// ---------------- tiling ----------------
#define TT      356              // output timesteps per tile
#define HALO    28               // 3 + 3*(1+2+4)
#define LL      (TT + HALO)      // 384 local positions
#define PITCH   388              // row pitch (floats); 388*4 = 1552 B (16B mult)
#define NTHREADS 256
#define NTILES  6                // ceil(2048/356)
#define PRED_ELEMS (BATCH*ND*NS*NV*T)        // 1,572,864
#define GUARD   16               // floats of scratch before bufA (negative-j reads)

typedef unsigned long long u64;

// ---- packed f32x2 helpers (Blackwell) ----
__device__ __forceinline__ u64 pk2(float a, float b) {
    u64 r; asm("mov.b64 %0, {%1, %2};" : "=l"(r) : "f"(a), "f"(b)); return r;
}
__device__ __forceinline__ u64 dup2f(float a) {
    u64 r; asm("mov.b64 %0, {%1, %1};" : "=l"(r) : "f"(a)); return r;
}
__device__ __forceinline__ void fma2(u64 &d, u64 a, u64 b) {
    asm("fma.rn.f32x2 %0, %1, %2, %0;" : "+l"(d) : "l"(a), "l"(b));
}
__device__ __forceinline__ void unpk(u64 v, float &lo, float &hi) {
    asm("mov.b64 {%0, %1}, %2;" : "=f"(lo), "=f"(hi) : "l"(v));
}

struct __align__(16) Smem {
    float bufs[GUARD + 2 * HID * PITCH]; // bufA, bufB back-to-back   49,728 B
    float xsb[4 + PITCH];                //                             1,568 B
    u64   whp[3][HID * 8 * KS];          // all 3 layers co-paired     12,288 B
    u64   woutp[HID * 6];                //                               768 B
    u64   boutp[6];                      //                                48 B
    float w_in[HID * KS];                //                               256 B
    float b_in[HID];                     //                                64 B
    float b_h[3 * HID];                  //                               192 B
};  // ~64.9 KB dynamic; x3 CTAs = ~195 KB/SM

// ---- hidden conv HID->HID dilation D, co-paired, J=3 j-vectors/warp ----
// warp: cg = wid>>2 -> co 8*cg..8*cg+7 (4 packed pairs);
//       q  = wid&3  -> j-vectors {q, q+4, q+8} (each 32 lane-contiguous j).
// Weights (8 broadcast LDS.128 per ci) amortized over 3 j-vectors (48 FFMA2).
template<int D, int S>
__device__ __forceinline__ void hidden_cp3(
    const float* __restrict__ in, float* __restrict__ out,
    const u64* __restrict__ wp, const float* __restrict__ bl,
    int gt0, int lane, int wid)
{
    const int cg = wid >> 2;
    const int q  = wid & 3;
    int jv[3];
    #pragma unroll
    for (int r = 0; r < 3; r++) jv[r] = (q + 4 * r) * 32 + lane;

    u64 acc[4][3];
    #pragma unroll
    for (int p = 0; p < 4; p++) {
        u64 bp = pk2(bl[cg * 8 + 2 * p], bl[cg * 8 + 2 * p + 1]);
        #pragma unroll
        for (int r = 0; r < 3; r++) acc[p][r] = bp;
    }

    #pragma unroll 2
    for (int ci = 0; ci < HID; ci++) {
        const float* row = in + ci * PITCH;
        u64 vd[3][4];
        #pragma unroll
        for (int r = 0; r < 3; r++)
            #pragma unroll
            for (int k = 0; k < 4; k++)
                vd[r][k] = dup2f(row[jv[r] + (k - 3) * D]);

        const ulonglong2* w2 = (const ulonglong2*)(wp + ci * 32 + cg * 16);
        #pragma unroll
        for (int p = 0; p < 4; p++) {
            ulonglong2 wa = w2[2 * p], wb = w2[2 * p + 1];
            #pragma unroll
            for (int r = 0; r < 3; r++) {
                fma2(acc[p][r], wa.x, vd[r][0]);
                fma2(acc[p][r], wa.y, vd[r][1]);
                fma2(acc[p][r], wb.x, vd[r][2]);
                fma2(acc[p][r], wb.y, vd[r][3]);
            }
        }
    }

    #pragma unroll
    for (int p = 0; p < 4; p++) {
        const int co0 = cg * 8 + 2 * p;
        #pragma unroll
        for (int r = 0; r < 3; r++) {
            float a0, a1; unpk(acc[p][r], a0, a1);
            int j = jv[r];
            if (j >= S) {
                bool z = (gt0 + j) < 0;
                out[co0 * PITCH + j]       = z ? 0.f : fmaxf(a0, 0.f);
                out[(co0 + 1) * PITCH + j] = z ? 0.f : fmaxf(a1, 0.f);
            }
        }
    }
}

__global__ void __launch_bounds__(NTHREADS, 3)
navar_main_kernel(const float* __restrict__ x,
                  const float* __restrict__ w_in, const float* __restrict__ b_in,
                  const float* __restrict__ w_h,  const float* __restrict__ b_h,
                  const float* __restrict__ w_out,const float* __restrict__ b_out,
                  float* __restrict__ out_contrib)
{
    extern __shared__ __align__(16) char smraw[];
    Smem& s = *reinterpret_cast<Smem*>(smraw);
    float* bufA = s.bufs + GUARD;
    float* bufB = bufA + HID * PITCH;
    float* xs   = s.xsb + 4;

    const int tile = blockIdx.x;
    const int g    = blockIdx.y;
    const int b    = blockIdx.z;
    const int t0   = tile * TT;
    const int gt0  = t0 - HALO;
    const int tid  = threadIdx.x;
    const int lane = tid & 31;
    const int wid  = tid >> 5;

    // ---- stage x tile + all params (all 3 hidden layers prestaged) ----
    const float* xg = x + ((size_t)b * GROUPS + g) * T;
    for (int j = tid; j < PITCH; j += NTHREADS) {
        int gt = gt0 + j;
        xs[j] = (gt >= 0 && gt < T) ? xg[gt] : 0.f;
    }
    if (tid < HID * KS) s.w_in[tid] = w_in[g * HID * KS + tid];
    if (tid < HID)      s.b_in[tid] = b_in[g * HID + tid];
    for (int i = tid; i < 3 * HID; i += NTHREADS) {
        int L = i >> 4, co = i & 15;
        s.b_h[i] = b_h[L * GROUPS * HID + g * HID + co];
    }
    for (int i = tid; i < HID * 6 * 2; i += NTHREADS) {
        int half = i & 1, dp = (i >> 1) % 6, ci = (i >> 1) / 6;
        ((float*)s.woutp)[i] = w_out[((size_t)g * NV + 2 * dp + half) * HID + ci];
    }
    if (tid < 12) {
        int half = tid & 1, dp = tid >> 1;
        ((float*)s.boutp)[tid] = b_out[g * NV + 2 * dp + half];
    }
    // hidden weights, co-paired: whp[L][(ci*8+pg)*4+k] = (w[2pg][ci][k], w[2pg+1][ci][k])
    #pragma unroll 1
    for (int L = 0; L < 3; L++) {
        const float* wsrc = w_h + ((size_t)L * GROUPS * HID + (size_t)g * HID) * (HID * KS);
        float* wdst = (float*)s.whp[L];
        #pragma unroll
        for (int r = 0; r < 4; r++) {
            int i = tid + r * NTHREADS;       // 0..1023
            int half = i & 1, k = (i >> 1) & 3, pg = (i >> 3) & 7, ci = i >> 6;
            wdst[i] = wsrc[((2 * pg + half) * HID + ci) * KS + k];
        }
    }
    __syncthreads();

    // ---- input conv 1 -> HID (thread = timestep j) -> bufA ----
    for (int j = tid; j < LL; j += NTHREADS) {
        float xv0 = xs[j - 3], xv1 = xs[j - 2], xv2 = xs[j - 1], xv3 = xs[j];
        const bool neg = (gt0 + j) < 0;
        #pragma unroll
        for (int co = 0; co < HID; co++) {
            float4 w = *(const float4*)(s.w_in + co * 4);
            float a = s.b_in[co];
            a = fmaf(w.x, xv0, a); a = fmaf(w.y, xv1, a);
            a = fmaf(w.z, xv2, a); a = fmaf(w.w, xv3, a);
            bufA[co * PITCH + j] = neg ? 0.f : fmaxf(a, 0.f);
        }
    }
    __syncthreads();

    hidden_cp3<1,  8>(bufA, bufB, s.whp[0], s.b_h,           gt0, lane, wid);
    __syncthreads();
    hidden_cp3<2, 16>(bufB, bufA, s.whp[1], s.b_h + HID,     gt0, lane, wid);
    __syncthreads();
    hidden_cp3<4, 28>(bufA, bufB, s.whp[2], s.b_h + 2 * HID, gt0, lane, wid);
    __syncthreads();

    // ---- 1x1 output conv: thread = timestep, 12 dst as 6 packed pairs ----
    {
        const int dd  = g / (NS * NV);
        const int rem = g % (NS * NV);
        const int ss  = rem / NV;
        const int src = rem % NV;
        const size_t cbase = ((size_t)((b * ND + dd) * NS + ss) * NV * NV + src) * T;

        for (int trel = tid; trel < TT; trel += NTHREADS) {
            const int gt = t0 + trel;
            if (gt >= T) break;
            const int jc = HALO + trel;

            u64 a6[6];
            #pragma unroll
            for (int dp = 0; dp < 6; dp++) a6[dp] = s.boutp[dp];

            #pragma unroll
            for (int ci = 0; ci < HID; ci++) {
                u64 hd = dup2f(bufB[ci * PITCH + jc]);
                const ulonglong2* w2 = (const ulonglong2*)(s.woutp + ci * 6);
                ulonglong2 wA = w2[0], wB = w2[1], wC = w2[2];
                fma2(a6[0], wA.x, hd); fma2(a6[1], wA.y, hd);
                fma2(a6[2], wB.x, hd); fma2(a6[3], wB.y, hd);
                fma2(a6[4], wC.x, hd); fma2(a6[5], wC.y, hd);
            }
            #pragma unroll
            for (int dp = 0; dp < 6; dp++) {
                float lo, hi; unpk(a6[dp], lo, hi);
                out_contrib[cbase + (size_t)(2 * dp)     * NV * T + gt] = lo;
                out_contrib[cbase + (size_t)(2 * dp + 1) * NV * T + gt] = hi;
            }
        }
    }
}

// prediction[b,dd,ss,v,t] = sum_src contrib[b,dd,ss,v,src,t] + biases[dd,ss,v]
__global__ void __launch_bounds__(256)
navar_pred_kernel(const float4* __restrict__ contrib4,
                  const float* __restrict__ biases,
                  float4* __restrict__ pred4)
{
    int idx = blockIdx.x * blockDim.x + threadIdx.x;
    if (idx >= PRED_ELEMS / 4) return;
    int t4 = idx & (T / 4 - 1);
    int r  = idx >> 9;                 // T/4 = 512
    float bsc = biases[r % (ND * NS * NV)];
    const float4* cp = contrib4 + (size_t)r * NV * (T / 4) + t4;
    float4 acc = make_float4(bsc, bsc, bsc, bsc);
    #pragma unroll
    for (int sI = 0; sI < NV; sI++) {
        float4 v = cp[(size_t)sI * (T / 4)];
        acc.x += v.x; acc.y += v.y; acc.z += v.z; acc.w += v.w;
    }
    pred4[idx] = acc;
}

extern "C" void kernel_launch(void* const* d_in, const int* in_sizes, int n_in,
                              void* d_out, int out_size)
{
    const float* x      = (const float*)d_in[0];
    const float* w_in   = (const float*)d_in[1];
    const float* b_in   = (const float*)d_in[2];
    const float* w_h    = (const float*)d_in[3];
    const float* b_h    = (const float*)d_in[4];
    const float* w_out  = (const float*)d_in[5];
    const float* b_out  = (const float*)d_in[6];
    const float* biases = (const float*)d_in[7];

    float* out     = (float*)d_out;
    float* pred    = out;                     // (B,ND,NS,NV,T)
    float* contrib = out + PRED_ELEMS;        // (B,ND,NS,NV,NV,T)

    const int smem_bytes = (int)sizeof(Smem);
    cudaFuncSetAttribute(navar_main_kernel,
                         cudaFuncAttributeMaxDynamicSharedMemorySize, smem_bytes);

    dim3 grid(NTILES, GROUPS, BATCH);
    navar_main_kernel<<<grid, NTHREADS, smem_bytes>>>(
        x, w_in, b_in, w_h, b_h, w_out, b_out, contrib);
    navar_pred_kernel<<<(PRED_ELEMS / 4 + 255) / 256, 256>>>(
        (const float4*)contrib, biases, (float4*)pred);
}

// round 9
// speedup vs baseline: 1.1567x; 1.0172x over previous
#include <cuda_runtime.h>

// ---------------- NAVAR dims ----------------
#define ND      2
#define NS      4
#define NV      12
#define HID     16
#define GROUPS  96
#define KS      4
#define T       2048
#define BATCH   8

// ---------------- tiling ----------------
#define TT      708              // output timesteps per tile
#define HALO    28               // 3 + 3*(1+2+4)
#define LL      (TT + HALO)      // 736 local positions = 23 * 32
#define NJ      23               // j-vectors of 32
#define PITCH   740              // row pitch (floats); 740*4 B is 16B-divisible
#define NTHREADS 256
#define NTILES  3                // 3*708 = 2124 >= 2048
#define PRED_ELEMS (BATCH*ND*NS*NV*T)        // 1,572,864
#define GUARD   16               // floats of scratch before bufA (negative-j reads)

typedef unsigned long long u64;

// ---- packed f32x2 helpers (Blackwell) ----
__device__ __forceinline__ u64 pk2(float a, float b) {
    u64 r; asm("mov.b64 %0, {%1, %2};" : "=l"(r) : "f"(a), "f"(b)); return r;
}
__device__ __forceinline__ u64 dup2f(float a) {
    u64 r; asm("mov.b64 %0, {%1, %1};" : "=l"(r) : "f"(a)); return r;
}
__device__ __forceinline__ void fma2(u64 &d, u64 a, u64 b) {
    asm("fma.rn.f32x2 %0, %1, %2, %0;" : "+l"(d) : "l"(a), "l"(b));
}
__device__ __forceinline__ void unpk(u64 v, float &lo, float &hi) {
    asm("mov.b64 {%0, %1}, %2;" : "=f"(lo), "=f"(hi) : "l"(v));
}

struct __align__(16) Smem {
    float bufs[GUARD + 2 * HID * PITCH]; // bufA, bufB back-to-back   94,784 B
    float xsb[4 + PITCH];                //                             2,976 B
    u64   whp[3][HID * 8 * KS];          // all 3 layers co-paired     12,288 B
    u64   woutp[HID * 6];                //                               768 B
    u64   boutp[6];                      //                                48 B
    float w_in[HID * KS];                //                               256 B
    float b_in[HID];                     //                                64 B
    float b_h[3 * HID];                  //                               192 B
};  // ~111.4 KB dynamic; x2 CTAs = ~222.8 KB/SM

// ---- hidden conv HID->HID dilation D, co-paired, up to 6 j-vectors/warp ----
// warp: cg = wid>>2 -> co 8*cg..8*cg+7 (4 packed pairs);
//       q  = wid&3  -> j-vectors {q + 4r : r < 6, q + 4r < NJ}.
// Weights (8 broadcast LDS.128 per ci) amortized over ~5.75 j-vectors.
template<int D, int S>
__device__ __forceinline__ void hidden_cp6(
    const float* __restrict__ in, float* __restrict__ out,
    const u64* __restrict__ wp, const float* __restrict__ bl,
    int gt0, int lane, int wid)
{
    const int cg = wid >> 2;
    const int q  = wid & 3;
    const int nr = (q + 20 < NJ) ? 6 : 5;    // q<3 -> 6 jvec, q==3 -> 5

    u64 acc[4][6];
    #pragma unroll
    for (int p = 0; p < 4; p++) {
        u64 bp = pk2(bl[cg * 8 + 2 * p], bl[cg * 8 + 2 * p + 1]);
        #pragma unroll
        for (int r = 0; r < 6; r++) acc[p][r] = bp;
    }

    #pragma unroll 1
    for (int ci = 0; ci < HID; ci++) {
        const float* row = in + ci * PITCH;
        const ulonglong2* w2 = (const ulonglong2*)(wp + ci * 32 + cg * 16);
        u64 w0x, w0y, w1x, w1y, w2x, w2y, w3x, w3y;
        { ulonglong2 t = w2[0]; w0x = t.x; w0y = t.y; }
        { ulonglong2 t = w2[1]; w1x = t.x; w1y = t.y; }
        u64 w4x, w4y, w5x, w5y, w6x, w6y, w7x, w7y;
        { ulonglong2 t = w2[2]; w2x = t.x; w2y = t.y; }
        { ulonglong2 t = w2[3]; w3x = t.x; w3y = t.y; }
        { ulonglong2 t = w2[4]; w4x = t.x; w4y = t.y; }
        { ulonglong2 t = w2[5]; w5x = t.x; w5y = t.y; }
        { ulonglong2 t = w2[6]; w6x = t.x; w6y = t.y; }
        { ulonglong2 t = w2[7]; w7x = t.x; w7y = t.y; }

        #pragma unroll
        for (int r = 0; r < 6; r++) {
            if (r < nr) {
                const int j = (q + 4 * r) * 32 + lane;
                u64 v0 = dup2f(row[j - 3 * D]);
                u64 v1 = dup2f(row[j - 2 * D]);
                u64 v2 = dup2f(row[j - 1 * D]);
                u64 v3 = dup2f(row[j]);
                fma2(acc[0][r], w0x, v0); fma2(acc[0][r], w0y, v1);
                fma2(acc[0][r], w1x, v2); fma2(acc[0][r], w1y, v3);
                fma2(acc[1][r], w2x, v0); fma2(acc[1][r], w2y, v1);
                fma2(acc[1][r], w3x, v2); fma2(acc[1][r], w3y, v3);
                fma2(acc[2][r], w4x, v0); fma2(acc[2][r], w4y, v1);
                fma2(acc[2][r], w5x, v2); fma2(acc[2][r], w5y, v3);
                fma2(acc[3][r], w6x, v0); fma2(acc[3][r], w6y, v1);
                fma2(acc[3][r], w7x, v2); fma2(acc[3][r], w7y, v3);
            }
        }
    }

    #pragma unroll
    for (int p = 0; p < 4; p++) {
        const int co0 = cg * 8 + 2 * p;
        #pragma unroll
        for (int r = 0; r < 6; r++) {
            if (r < nr) {
                const int j = (q + 4 * r) * 32 + lane;
                if (j >= S) {
                    float a0, a1; unpk(acc[p][r], a0, a1);
                    bool z = (gt0 + j) < 0;
                    out[co0 * PITCH + j]       = z ? 0.f : fmaxf(a0, 0.f);
                    out[(co0 + 1) * PITCH + j] = z ? 0.f : fmaxf(a1, 0.f);
                }
            }
        }
    }
}

__global__ void __launch_bounds__(NTHREADS, 2)
navar_main_kernel(const float* __restrict__ x,
                  const float* __restrict__ w_in, const float* __restrict__ b_in,
                  const float* __restrict__ w_h,  const float* __restrict__ b_h,
                  const float* __restrict__ w_out,const float* __restrict__ b_out,
                  float* __restrict__ out_contrib)
{
    extern __shared__ __align__(16) char smraw[];
    Smem& s = *reinterpret_cast<Smem*>(smraw);
    float* bufA = s.bufs + GUARD;
    float* bufB = bufA + HID * PITCH;
    float* xs   = s.xsb + 4;

    const int tile = blockIdx.x;
    const int g    = blockIdx.y;
    const int b    = blockIdx.z;
    const int t0   = tile * TT;
    const int gt0  = t0 - HALO;
    const int tid  = threadIdx.x;
    const int lane = tid & 31;
    const int wid  = tid >> 5;

    // ---- stage x tile + all params (all 3 hidden layers prestaged) ----
    const float* xg = x + ((size_t)b * GROUPS + g) * T;
    for (int j = tid; j < PITCH; j += NTHREADS) {
        int gt = gt0 + j;
        xs[j] = (gt >= 0 && gt < T) ? xg[gt] : 0.f;
    }
    if (tid < HID * KS) s.w_in[tid] = w_in[g * HID * KS + tid];
    if (tid < HID)      s.b_in[tid] = b_in[g * HID + tid];
    for (int i = tid; i < 3 * HID; i += NTHREADS) {
        int L = i >> 4, co = i & 15;
        s.b_h[i] = b_h[L * GROUPS * HID + g * HID + co];
    }
    for (int i = tid; i < HID * 6 * 2; i += NTHREADS) {
        int half = i & 1, dp = (i >> 1) % 6, ci = (i >> 1) / 6;
        ((float*)s.woutp)[i] = w_out[((size_t)g * NV + 2 * dp + half) * HID + ci];
    }
    if (tid < 12) {
        int half = tid & 1, dp = tid >> 1;
        ((float*)s.boutp)[tid] = b_out[g * NV + 2 * dp + half];
    }
    // hidden weights, co-paired: whp[L][(ci*8+pg)*4+k] = (w[2pg][ci][k], w[2pg+1][ci][k])
    #pragma unroll 1
    for (int L = 0; L < 3; L++) {
        const float* wsrc = w_h + ((size_t)L * GROUPS * HID + (size_t)g * HID) * (HID * KS);
        float* wdst = (float*)s.whp[L];
        #pragma unroll
        for (int r = 0; r < 4; r++) {
            int i = tid + r * NTHREADS;       // 0..1023
            int half = i & 1, k = (i >> 1) & 3, pg = (i >> 3) & 7, ci = i >> 6;
            wdst[i] = wsrc[((2 * pg + half) * HID + ci) * KS + k];
        }
    }
    __syncthreads();

    // ---- input conv 1 -> HID (thread = timestep j) -> bufA ----
    for (int j = tid; j < LL; j += NTHREADS) {
        float xv0 = xs[j - 3], xv1 = xs[j - 2], xv2 = xs[j - 1], xv3 = xs[j];
        const bool neg = (gt0 + j) < 0;
        #pragma unroll
        for (int co = 0; co < HID; co++) {
            float4 w = *(const float4*)(s.w_in + co * 4);
            float a = s.b_in[co];
            a = fmaf(w.x, xv0, a); a = fmaf(w.y, xv1, a);
            a = fmaf(w.z, xv2, a); a = fmaf(w.w, xv3, a);
            bufA[co * PITCH + j] = neg ? 0.f : fmaxf(a, 0.f);
        }
    }
    __syncthreads();

    hidden_cp6<1,  8>(bufA, bufB, s.whp[0], s.b_h,           gt0, lane, wid);
    __syncthreads();
    hidden_cp6<2, 16>(bufB, bufA, s.whp[1], s.b_h + HID,     gt0, lane, wid);
    __syncthreads();
    hidden_cp6<4, 28>(bufA, bufB, s.whp[2], s.b_h + 2 * HID, gt0, lane, wid);
    __syncthreads();

    // ---- 1x1 output conv: thread = timestep, 12 dst as 6 packed pairs ----
    {
        const int dd  = g / (NS * NV);
        const int rem = g % (NS * NV);
        const int ss  = rem / NV;
        const int src = rem % NV;
        const size_t cbase = ((size_t)((b * ND + dd) * NS + ss) * NV * NV + src) * T;

        for (int trel = tid; trel < TT; trel += NTHREADS) {
            const int gt = t0 + trel;
            if (gt >= T) break;
            const int jc = HALO + trel;

            u64 a6[6];
            #pragma unroll
            for (int dp = 0; dp < 6; dp++) a6[dp] = s.boutp[dp];

            #pragma unroll
            for (int ci = 0; ci < HID; ci++) {
                u64 hd = dup2f(bufB[ci * PITCH + jc]);
                const ulonglong2* w2 = (const ulonglong2*)(s.woutp + ci * 6);
                ulonglong2 wA = w2[0], wB = w2[1], wC = w2[2];
                fma2(a6[0], wA.x, hd); fma2(a6[1], wA.y, hd);
                fma2(a6[2], wB.x, hd); fma2(a6[3], wB.y, hd);
                fma2(a6[4], wC.x, hd); fma2(a6[5], wC.y, hd);
            }
            #pragma unroll
            for (int dp = 0; dp < 6; dp++) {
                float lo, hi; unpk(a6[dp], lo, hi);
                out_contrib[cbase + (size_t)(2 * dp)     * NV * T + gt] = lo;
                out_contrib[cbase + (size_t)(2 * dp + 1) * NV * T + gt] = hi;
            }
        }
    }
}

// prediction[b,dd,ss,v,t] = sum_src contrib[b,dd,ss,v,src,t] + biases[dd,ss,v]
__global__ void __launch_bounds__(256)
navar_pred_kernel(const float4* __restrict__ contrib4,
                  const float* __restrict__ biases,
                  float4* __restrict__ pred4)
{
    int idx = blockIdx.x * blockDim.x + threadIdx.x;
    if (idx >= PRED_ELEMS / 4) return;
    int t4 = idx & (T / 4 - 1);
    int r  = idx >> 9;                 // T/4 = 512
    float bsc = biases[r % (ND * NS * NV)];
    const float4* cp = contrib4 + (size_t)r * NV * (T / 4) + t4;
    float4 acc = make_float4(bsc, bsc, bsc, bsc);
    #pragma unroll
    for (int sI = 0; sI < NV; sI++) {
        float4 v = cp[(size_t)sI * (T / 4)];
        acc.x += v.x; acc.y += v.y; acc.z += v.z; acc.w += v.w;
    }
    pred4[idx] = acc;
}

extern "C" void kernel_launch(void* const* d_in, const int* in_sizes, int n_in,
                              void* d_out, int out_size)
{
    const float* x      = (const float*)d_in[0];
    const float* w_in   = (const float*)d_in[1];
    const float* b_in   = (const float*)d_in[2];
    const float* w_h    = (const float*)d_in[3];
    const float* b_h    = (const float*)d_in[4];
    const float* w_out  = (const float*)d_in[5];
    const float* b_out  = (const float*)d_in[6];
    const float* biases = (const float*)d_in[7];

    float* out     = (float*)d_out;
    float* pred    = out;                     // (B,ND,NS,NV,T)
    float* contrib = out + PRED_ELEMS;        // (B,ND,NS,NV,NV,T)

    const int smem_bytes = (int)sizeof(Smem);
    cudaFuncSetAttribute(navar_main_kernel,
                         cudaFuncAttributeMaxDynamicSharedMemorySize, smem_bytes);

    dim3 grid(NTILES, GROUPS, BATCH);
    navar_main_kernel<<<grid, NTHREADS, smem_bytes>>>(
        x, w_in, b_in, w_h, b_h, w_out, b_out, contrib);
    navar_pred_kernel<<<(PRED_ELEMS / 4 + 255) / 256, 256>>>(
        (const float4*)contrib, biases, (float4*)pred);
}